// round 17
// baseline (speedup 1.0000x reference)
#include <cuda_runtime.h>
#include <cuda_fp16.h>
#include <math.h>
#include <stdint.h>

#define B_ 2
#define T_ 2048
#define C_ 1024
#define H_ 16
#define D_ 64
#define M_ 4096
#define K2L 0.18033688f   // 0.125 * log2(e)

// Scratch (allocation-free), all fp16
__device__ __half g_xh[M_*C_];
__device__ __half g_Wh[4*C_*C_];
__device__ __half g_Q [M_*C_];
__device__ __half g_K [M_*C_];
__device__ __half g_V [M_*C_];
__device__ __half g_Vt[B_*H_*D_*T_];
__device__ __half g_AO[M_*C_];

// ---------------------------------------------------------------------------
__device__ __forceinline__ uint32_t s2u(const void* p) {
    return (uint32_t)__cvta_generic_to_shared(p);
}
__device__ __forceinline__ void cpa16(uint32_t d, const void* s) {
    asm volatile("cp.async.cg.shared.global [%0], [%1], 16;\n" :: "r"(d), "l"(s));
}
#define CPCOMMIT() asm volatile("cp.async.commit_group;\n")
#define CPWAIT0()  asm volatile("cp.async.wait_group 0;\n")
__device__ __forceinline__ float ex2f(float x) {
    float y; asm("ex2.approx.ftz.f32 %0, %1;" : "=f"(y) : "f"(x)); return y;
}
__device__ __forceinline__ uint32_t packh(float lo, float hi) {
    __half2 h = __floats2half2_rn(lo, hi);
    return *(uint32_t*)&h;
}
__device__ __forceinline__ uint32_t ex2h2(uint32_t x) {
    uint32_t r; asm("ex2.approx.f16x2 %0, %1;" : "=r"(r) : "r"(x)); return r;
}
// fp16 m16n8k16, fp32 accumulate
__device__ __forceinline__ void mma_f16(float* c, const uint32_t* a, const uint32_t* b) {
    asm volatile(
        "mma.sync.aligned.m16n8k16.row.col.f32.f16.f16.f32 "
        "{%0,%1,%2,%3}, {%4,%5,%6,%7}, {%8,%9}, {%0,%1,%2,%3};\n"
        : "+f"(c[0]), "+f"(c[1]), "+f"(c[2]), "+f"(c[3])
        : "r"(a[0]), "r"(a[1]), "r"(a[2]), "r"(a[3]), "r"(b[0]), "r"(b[1]));
}

// ---------------------------------------------------------------------------
// Prepass (merged): fp32 -> fp16, perm16 within 16-groups.
// grid.y 0..3 -> x chunks; 4..7 -> W[y-4]. Each slice = 1M elements.
// ---------------------------------------------------------------------------
__device__ __forceinline__ void prep16(const float* __restrict__ s, __half* __restrict__ d) {
    float v[16];
    *(float4*)(v)      = *(const float4*)(s);
    *(float4*)(v + 4)  = *(const float4*)(s + 4);
    *(float4*)(v + 8)  = *(const float4*)(s + 8);
    *(float4*)(v + 12) = *(const float4*)(s + 12);
    uint32_t o[8];
    #pragma unroll
    for (int t = 0; t < 4; t++) {
        o[2*t]     = packh(v[2*t],     v[2*t + 1]);
        o[2*t + 1] = packh(v[2*t + 8], v[2*t + 9]);
    }
    *(uint4*)(d)     = make_uint4(o[0], o[1], o[2], o[3]);
    *(uint4*)(d + 8) = make_uint4(o[4], o[5], o[6], o[7]);
}
__global__ void prep_all(const float* x, const float* w0, const float* w1,
                         const float* w2, const float* w3) {
    const int y = blockIdx.y;
    const float* src;
    __half* dst;
    if (y < 4) { src = x + (long)y * (C_ * C_);        dst = g_xh + (long)y * (C_ * C_); }
    else       { src = (y == 4) ? w0 : (y == 5) ? w1 : (y == 6) ? w2 : w3;
                 dst = g_Wh + (long)(y - 4) * (C_ * C_);
                 src += 0; }
    int i = (blockIdx.x * blockDim.x + threadIdx.x) * 16;
    prep16(src + i, dst + i);
}

// ---------------------------------------------------------------------------
// GEMM-NT fp16 m16n8k16 (validated R14). MODE 0: fp32 out. MODE 3: fused QKV.
// ---------------------------------------------------------------------------
#define GP 96
#define GTILE (128 * GP)
#define GEMM_SMEM (4 * GTILE)

template<int MODE>
__global__ void __launch_bounds__(256)
gemm_tc(const __half* __restrict__ A, const __half* __restrict__ Bm,
        float* __restrict__ Cm, __half* __restrict__ Cq,
        __half* __restrict__ Ck, __half* __restrict__ Cv)
{
    extern __shared__ char sm[];
    char* As = sm;
    char* Bs = sm + 2 * GTILE;

    const int tid = threadIdx.x, lane = tid & 31, warp = tid >> 5;
    const int gid = lane >> 2, tig = lane & 3;
    const int wm = warp & 3, wn = warp >> 2;
    const int bm = blockIdx.y * 128, bn = blockIdx.x * 128;

    float acc[2][8][4];
    #pragma unroll
    for (int mt = 0; mt < 2; mt++)
        #pragma unroll
        for (int nt = 0; nt < 8; nt++)
            #pragma unroll
            for (int e = 0; e < 4; e++) acc[mt][nt][e] = 0.f;

    auto loadst = [&](int s, int kt) {
        #pragma unroll
        for (int t = 0; t < 2; t++) {
            int id = tid + t * 256;
            int row = id >> 2, seg = id & 3;
            cpa16(s2u(As + s * GTILE + row * GP + seg * 16),
                  A + (long)(bm + row) * C_ + kt + seg * 8);
            cpa16(s2u(Bs + s * GTILE + row * GP + seg * 16),
                  Bm + (long)(bn + row) * C_ + kt + seg * 8);
        }
    };

    loadst(0, 0); CPCOMMIT();

    #pragma unroll 2
    for (int t = 0; t < 32; t++) {
        CPWAIT0(); __syncthreads();
        if (t + 1 < 32) { loadst((t + 1) & 1, (t + 1) * 32); CPCOMMIT(); }
        const char* as = As + (t & 1) * GTILE;
        const char* bs = Bs + (t & 1) * GTILE;
        #pragma unroll
        for (int ck = 0; ck < 2; ck++) {
            int co = ck * 32 + tig * 8;
            uint32_t a[2][4];
            #pragma unroll
            for (int mt = 0; mt < 2; mt++) {
                int r = wm * 32 + mt * 16 + gid;
                uint2 lo = *(const uint2*)(as + r * GP + co);
                uint2 hi = *(const uint2*)(as + (r + 8) * GP + co);
                a[mt][0] = lo.x; a[mt][1] = hi.x; a[mt][2] = lo.y; a[mt][3] = hi.y;
            }
            #pragma unroll
            for (int nt = 0; nt < 8; nt++) {
                int r = wn * 64 + nt * 8 + gid;
                uint2 bv = *(const uint2*)(bs + r * GP + co);
                uint32_t b[2] = { bv.x, bv.y };
                mma_f16(acc[0][nt], a[0], b);
                mma_f16(acc[1][nt], a[1], b);
            }
        }
    }

    #pragma unroll
    for (int mt = 0; mt < 2; mt++) {
        #pragma unroll
        for (int nt = 0; nt < 8; nt++) {
            int r1 = bm + wm * 32 + mt * 16 + gid;
            int r2 = r1 + 8;
            int n0 = bn + wn * 64 + nt * 8 + 2 * tig;
            if (MODE == 0) {
                *(float2*)&Cm[(long)r1 * C_ + n0] = make_float2(acc[mt][nt][0], acc[mt][nt][1]);
                *(float2*)&Cm[(long)r2 * C_ + n0] = make_float2(acc[mt][nt][2], acc[mt][nt][3]);
            } else {
                int w  = n0 >> 10;          // 0=Q, 1=K, 2=V
                int nc = n0 & 1023;
                if (w == 2) {
                    *(uint32_t*)&Cv[(long)r1 * C_ + nc] = packh(acc[mt][nt][0], acc[mt][nt][1]);
                    *(uint32_t*)&Cv[(long)r2 * C_ + nc] = packh(acc[mt][nt][2], acc[mt][nt][3]);
                } else {
                    __half* dst = (w == 0) ? Cq : Ck;
                    int pp = (nc & ~15) | (4 * tig + 2 * ((nc >> 3) & 1));   // perm16 pair pos
                    *(uint32_t*)&dst[(long)r1 * C_ + pp] = packh(acc[mt][nt][0], acc[mt][nt][1]);
                    *(uint32_t*)&dst[(long)r2 * C_ + pp] = packh(acc[mt][nt][2], acc[mt][nt][3]);
                }
            }
        }
    }
}

// ---------------------------------------------------------------------------
// V transpose fp16 (validated R14).
// ---------------------------------------------------------------------------
__global__ void vtrans()
{
    __shared__ __half tile[32][36];
    const int t0 = blockIdx.x * 32, c0 = blockIdx.y * 32, b = blockIdx.z;
    const int tid = threadIdx.x;

    {
        int row = tid >> 3, seg = tid & 7;
        *(uint2*)&tile[row][seg * 4] =
            *(const uint2*)&g_V[(long)(b * T_ + t0 + row) * C_ + c0 + seg * 4];
    }
    __syncthreads();

    const int u = tid & 15, dc = tid >> 4;
    const int pos = 16 * (u >> 3) + 4 * (u & 3) + 2 * ((u >> 2) & 1);
    #pragma unroll
    for (int r = 0; r < 2; r++) {
        int d = dc + r * 16;
        __half2 val = __halves2half2(tile[2 * u][d], tile[2 * u + 1][d]);
        int cc = c0 + d, h = cc >> 6, dd = cc & 63;
        *(uint32_t*)&g_Vt[(long)(((b << 4) + h) * 64 + dd) * T_ + t0 + pos] =
            *(uint32_t*)&val;
    }
}

// ---------------------------------------------------------------------------
// Flash attention (causal), fp16 m16n8k16 (validated R16) + NEW diagonal
// sub-tile skipping: per-strip lim = m0+mt*16+15-dd bounds the live n-groups
// (S) and k-chunks (PV/racc); skipped work is exactly zero.
// ---------------------------------------------------------------------------
#define AP 160
#define AQ_BYTES  (128 * AP)
#define K64_BYTES (64 * AP)
#define V72_BYTES (72 * AP)
#define ATTN_SMEM (AQ_BYTES + 2 * K64_BYTES + 2 * V72_BYTES)

__global__ void __launch_bounds__(128, 2)
attn_tc()
{
    extern __shared__ char sm[];
    char* Qs  = sm;
    char* Kst = sm + AQ_BYTES;
    char* Vst = sm + AQ_BYTES + 2 * K64_BYTES;

    const int qb = gridDim.x - 1 - blockIdx.x;    // big tiles first
    const int bh = blockIdx.y, bb = bh >> 4, h = bh & 15;
    const int tid = threadIdx.x, lane = tid & 31, warp = tid >> 5;
    const int gid = lane >> 2, tig = lane & 3;
    const int m0 = warp * 32;
    const int co0 = tig * 8;

    const long kbase0 = ((long)(bb * T_)) * C_ + h * 64;
    const long vbase0 = ((long)((bb * 16 + h) * 64)) * T_;

    auto load_kv = [&](int kb, int s) {
        char* Ks = Kst + s * K64_BYTES;
        char* Vs = Vst + s * V72_BYTES;
        const long kbase = kbase0 + (long)(kb * 64) * C_;
        const long vbase = vbase0 + kb * 64;
        #pragma unroll
        for (int j = 0; j < 4; j++) {
            int id = tid + j * 128;
            int row = id >> 3, seg = id & 7;
            cpa16(s2u(Ks + row * AP + seg * 16), g_K  + kbase + (long)row * C_ + seg * 8);
            cpa16(s2u(Vs + row * AP + seg * 16), g_Vt + vbase + (long)row * T_ + seg * 8);
        }
    };

    // Prologue: Q (128 rows) + KV tile 0; ones rows (64-71) of both V stages.
    #pragma unroll
    for (int j = 0; j < 8; j++) {
        int id = tid + j * 128;
        int row = id >> 3, seg = id & 7;
        cpa16(s2u(Qs + row * AP + seg * 16),
              g_Q + kbase0 + (long)(qb * 128 + row) * C_ + seg * 8);
    }
    load_kv(0, 0);
    CPCOMMIT();
    {
        int s = tid >> 6, r = (tid >> 3) & 7, seg = tid & 7;
        uint4 one4 = make_uint4(0x3C003C00u, 0x3C003C00u, 0x3C003C00u, 0x3C003C00u);
        *(uint4*)(Vst + s * V72_BYTES + (64 + r) * AP + seg * 16) = one4;
    }

    float mr[2][2];
    #pragma unroll
    for (int mt = 0; mt < 2; mt++) { mr[mt][0] = -INFINITY; mr[mt][1] = -INFINITY; }
    float oacc[2][8][4], racc[2][4];
    #pragma unroll
    for (int mt = 0; mt < 2; mt++) {
        #pragma unroll
        for (int nt = 0; nt < 8; nt++)
            #pragma unroll
            for (int e = 0; e < 4; e++) oacc[mt][nt][e] = 0.f;
        #pragma unroll
        for (int e = 0; e < 4; e++) racc[mt][e] = 0.f;
    }

    const int nkb = 2 * qb + 2;
    for (int kb = 0; kb < nkb; kb++) {
        const int s = kb & 1;
        char* Ks = Kst + s * K64_BYTES;
        char* Vs = Vst + s * V72_BYTES;

        CPWAIT0();
        __syncthreads();
        if (kb + 1 < nkb) { load_kv(kb + 1, s ^ 1); CPCOMMIT(); }

        if (kb == nkb - 1 && m0 < 64) continue;   // fully masked warp-tile

        const int dd = (kb - 2 * qb) * 64;
        const bool diag = (kb >= 2 * qb);
        // live-column bound per m16 strip (warp-uniform); 63 = all live
        const int lim0 = diag ? (m0 + 15 - dd)      : 63;
        const int lim1 = diag ? (m0 + 16 + 15 - dd) : 63;

        // ---- S = Q @ K^T (skip n-groups beyond lim) ----
        float sacc[2][8][4];
        #pragma unroll
        for (int mt = 0; mt < 2; mt++)
            #pragma unroll
            for (int nt = 0; nt < 8; nt++)
                #pragma unroll
                for (int e = 0; e < 4; e++) sacc[mt][nt][e] = 0.f;

        #pragma unroll
        for (int ck = 0; ck < 4; ck++) {
            int co = ck * 32 + co0;
            uint32_t a[2][4];
            #pragma unroll
            for (int mt = 0; mt < 2; mt++) {
                int r = m0 + mt * 16 + gid;
                uint2 lo = *(const uint2*)(Qs + r * AP + co);
                uint2 hi = *(const uint2*)(Qs + (r + 8) * AP + co);
                a[mt][0] = lo.x; a[mt][1] = hi.x; a[mt][2] = lo.y; a[mt][3] = hi.y;
            }
            #pragma unroll
            for (int nt = 0; nt < 8; nt++) {
                uint2 bv = *(const uint2*)(Ks + (nt * 8 + gid) * AP + co);
                uint32_t b[2] = { bv.x, bv.y };
                if (nt * 8 <= lim0) mma_f16(sacc[0][nt], a[0], b);
                if (nt * 8 <= lim1) mma_f16(sacc[1][nt], a[1], b);
            }
        }

        // ---- softmax: scale+mask, max, then f16x2 exp straight into A-frags ----
        uint32_t pfrag[2][4][4];
        #pragma unroll
        for (int mt = 0; mt < 2; mt++) {
            const int lim = mt ? lim1 : lim0;
            float mx0 = -INFINITY, mx1 = -INFINITY;
            #pragma unroll
            for (int nt = 0; nt < 8; nt++) {
                if (nt * 8 > lim) continue;
                #pragma unroll
                for (int e = 0; e < 4; e++) {
                    float sv = sacc[mt][nt][e] * K2L;
                    if (diag) {
                        int rl = m0 + mt * 16 + gid + ((e >> 1) << 3);
                        int cl = nt * 8 + 2 * tig + (e & 1);
                        if (cl + dd > rl) sv = -INFINITY;
                    }
                    sacc[mt][nt][e] = sv;
                }
                mx0 = fmaxf(mx0, fmaxf(sacc[mt][nt][0], sacc[mt][nt][1]));
                mx1 = fmaxf(mx1, fmaxf(sacc[mt][nt][2], sacc[mt][nt][3]));
            }
            mx0 = fmaxf(mx0, __shfl_xor_sync(~0u, mx0, 1));
            mx0 = fmaxf(mx0, __shfl_xor_sync(~0u, mx0, 2));
            mx1 = fmaxf(mx1, __shfl_xor_sync(~0u, mx1, 1));
            mx1 = fmaxf(mx1, __shfl_xor_sync(~0u, mx1, 2));
            float mn0 = fmaxf(mr[mt][0], mx0), mn1 = fmaxf(mr[mt][1], mx1);
            float al0 = ex2f(mr[mt][0] - mn0), al1 = ex2f(mr[mt][1] - mn1);
            mr[mt][0] = mn0;  mr[mt][1] = mn1;
            #pragma unroll
            for (int nt = 0; nt < 8; nt++) {
                if (nt * 8 > lim) {
                    pfrag[mt][nt >> 1][(nt & 1) * 2 + 0] = 0u;
                    pfrag[mt][nt >> 1][(nt & 1) * 2 + 1] = 0u;
                } else {
                    uint32_t lo = packh(sacc[mt][nt][0] - mn0, sacc[mt][nt][1] - mn0);
                    uint32_t hi = packh(sacc[mt][nt][2] - mn1, sacc[mt][nt][3] - mn1);
                    pfrag[mt][nt >> 1][(nt & 1) * 2 + 0] = ex2h2(lo);
                    pfrag[mt][nt >> 1][(nt & 1) * 2 + 1] = ex2h2(hi);
                }
            }
            #pragma unroll
            for (int nt = 0; nt < 8; nt++) {
                oacc[mt][nt][0] *= al0; oacc[mt][nt][1] *= al0;
                oacc[mt][nt][2] *= al1; oacc[mt][nt][3] *= al1;
            }
            racc[mt][0] *= al0; racc[mt][1] *= al0;
            racc[mt][2] *= al1; racc[mt][3] *= al1;
        }

        // ---- O += P @ V; l += P @ ones (skip k-chunks beyond lim) ----
        #pragma unroll
        for (int ck = 0; ck < 4; ck++) {
            int co = ck * 32 + co0;
            const bool live0 = (ck * 16 <= lim0), live1 = (ck * 16 <= lim1);
            if (!live0 && !live1) continue;
            #pragma unroll
            for (int nt = 0; nt < 8; nt++) {
                uint2 bv = *(const uint2*)(Vs + (nt * 8 + gid) * AP + co);
                uint32_t b[2] = { bv.x, bv.y };
                if (live0) mma_f16(oacc[0][nt], pfrag[0][ck], b);
                if (live1) mma_f16(oacc[1][nt], pfrag[1][ck], b);
            }
            uint2 bo = *(const uint2*)(Vs + (64 + gid) * AP + co);
            uint32_t b1[2] = { bo.x, bo.y };
            if (live0) mma_f16(racc[0], pfrag[0][ck], b1);
            if (live1) mma_f16(racc[1], pfrag[1][ck], b1);
        }
    }

    // ---- finalize: l from racc (all cols equal); AO fp16 perm16 ----
    #pragma unroll
    for (int mt = 0; mt < 2; mt++) {
        float inv0 = 1.f / racc[mt][0], inv1 = 1.f / racc[mt][2];
        long base = ((long)(bb * T_ + qb * 128 + m0 + mt * 16 + gid)) * C_ + h * 64;
        #pragma unroll
        for (int nt = 0; nt < 8; nt++) {
            int pp = (nt >> 1) * 16 + 4 * tig + 2 * (nt & 1);
            *(uint32_t*)&g_AO[base + pp] =
                packh(oacc[mt][nt][0] * inv0, oacc[mt][nt][1] * inv0);
            *(uint32_t*)&g_AO[base + 8L * C_ + pp] =
                packh(oacc[mt][nt][2] * inv1, oacc[mt][nt][3] * inv1);
        }
    }
}

// ---------------------------------------------------------------------------
extern "C" void kernel_launch(void* const* d_in, const int* in_sizes, int n_in,
                              void* d_out, int out_size)
{
    const float* x  = (const float*)d_in[0];
    const float* Wq = (const float*)d_in[1];
    const float* Wk = (const float*)d_in[2];
    const float* Wv = (const float*)d_in[3];
    const float* Wo = (const float*)d_in[4];
    float* out = (float*)d_out;

    __half *xh, *Wh, *Q, *K, *V, *AO;
    cudaGetSymbolAddress((void**)&xh, g_xh);
    cudaGetSymbolAddress((void**)&Wh, g_Wh);
    cudaGetSymbolAddress((void**)&Q,  g_Q);
    cudaGetSymbolAddress((void**)&K,  g_K);
    cudaGetSymbolAddress((void**)&V,  g_V);
    cudaGetSymbolAddress((void**)&AO, g_AO);

    cudaFuncSetAttribute(gemm_tc<0>, cudaFuncAttributeMaxDynamicSharedMemorySize, GEMM_SMEM);
    cudaFuncSetAttribute(gemm_tc<3>, cudaFuncAttributeMaxDynamicSharedMemorySize, GEMM_SMEM);
    cudaFuncSetAttribute(attn_tc,    cudaFuncAttributeMaxDynamicSharedMemorySize, ATTN_SMEM);

    prep_all<<<dim3(256, 8), 256>>>(x, Wq, Wk, Wv, Wo);

    // Fused QKV projection: B = [Wq; Wk; Wv] rows 0..3071 of g_Wh.
    gemm_tc<3><<<dim3(24, 32), 256, GEMM_SMEM>>>(xh, Wh, nullptr, Q, K, V);

    vtrans<<<dim3(T_ / 32, C_ / 32, B_), 256>>>();

    attn_tc<<<dim3(T_ / 128, B_ * H_), 128, ATTN_SMEM>>>();

    gemm_tc<0><<<dim3(8, 32), 256, GEMM_SMEM>>>(AO, Wh + 3L * C_ * C_, out,
                                                nullptr, nullptr, nullptr);
}